// round 1
// baseline (speedup 1.0000x reference)
#include <cuda_runtime.h>
#include <cstdint>

#define SLOPE 0.01f
#define BN_EPS 1e-5f

// Fixed problem sizes (from setup_inputs): N_in=80000, N_out=200000, Cin=128, Cout=64
#define MAX_NIN   80000
#define MAX_NOUT  200000
#define RED_BLOCKS 240

// Scratch (static device globals — no allocation allowed)
__device__ float g_h [MAX_NIN  * 64];
__device__ float g_u [MAX_NOUT * 64];
__device__ float g_t1[MAX_NOUT * 64];
__device__ float g_t2[MAX_NOUT * 64];
__device__ float g_t3[MAX_NOUT * 64];
__device__ float g_part[RED_BLOCKS * 128];
__device__ float g_ab[4 * 128];   // per BN stage: a[64], b[64]

// ---------------------------------------------------------------------------
// Gather-GEMM conv:  out[n,d] = sum_k sum_c feats[nbr[k,n], c] * W[k,c,d]
// Optional affine (fused BN of previous stage) applied to gathered values;
// sentinel idx >= Nsrc yields exact zero row (matches reference pad order).
// MODE 0: out = lrelu(acc)   MODE 1: out = acc + skip
// Block: 64 output points x 64 Cout, 256 threads, 4x4 microtile.
// ---------------------------------------------------------------------------
template<int KK, int CIN, bool AFF, int MODE>
__global__ __launch_bounds__(256)
void conv_kernel(const float* __restrict__ feats,
                 const float* __restrict__ W,
                 const int*   __restrict__ nbr,
                 const float* __restrict__ ab,
                 const float* __restrict__ skip,
                 float*       __restrict__ out,
                 int Nsrc, int Nout)
{
    __shared__ float As[64][68];   // [row][c] (padded)
    __shared__ float Bs[64][64];   // [c][d]
    __shared__ int   sIdx[64];
    __shared__ float sA[64], sB[64];

    const int tid = threadIdx.x;
    const int tx  = tid & 15;      // cout group (4 couts)
    const int ty  = tid >> 4;      // row group  (4 rows)
    const int n0  = blockIdx.x * 64;

    float acc[4][4];
    #pragma unroll
    for (int i = 0; i < 4; ++i)
        #pragma unroll
        for (int j = 0; j < 4; ++j) acc[i][j] = 0.f;

    if (AFF && tid < 64) { sA[tid] = ab[tid]; sB[tid] = ab[64 + tid]; }

    for (int k = 0; k < KK; ++k) {
        if (tid < 64) sIdx[tid] = nbr[k * Nout + n0 + tid];
        __syncthreads();

        #pragma unroll
        for (int chunk = 0; chunk < CIN; chunk += 64) {
            // --- gather A tile: 64 rows x 64 cols (this Cin chunk) ---
            #pragma unroll
            for (int i = 0; i < 4; ++i) {
                const int row = (tid >> 4) + i * 16;
                const int cg  = tid & 15;
                const int idx = sIdx[row];
                float4 v;
                if (idx < Nsrc) {
                    v = *(const float4*)&feats[(long long)idx * CIN + chunk + cg * 4];
                    if (AFF) {   // only for CIN==64 stages (chunk==0)
                        const int c = cg * 4;
                        v.x = v.x * sA[c + 0] + sB[c + 0];
                        v.y = v.y * sA[c + 1] + sB[c + 1];
                        v.z = v.z * sA[c + 2] + sB[c + 2];
                        v.w = v.w * sA[c + 3] + sB[c + 3];
                    }
                } else {
                    v = make_float4(0.f, 0.f, 0.f, 0.f);
                }
                *(float4*)&As[row][cg * 4] = v;
            }
            // --- load W tile: 64 x 64 ---
            {
                const float4* Wk = (const float4*)(W + ((long long)k * CIN + chunk) * 64);
                float4* Bp = (float4*)&Bs[0][0];
                #pragma unroll
                for (int i = 0; i < 4; ++i)
                    Bp[tid + i * 256] = Wk[tid + i * 256];
            }
            __syncthreads();

            // --- 64x64x64 FFMA core ---
            #pragma unroll
            for (int cc = 0; cc < 64; ++cc) {
                const float a0 = As[ty * 4 + 0][cc];
                const float a1 = As[ty * 4 + 1][cc];
                const float a2 = As[ty * 4 + 2][cc];
                const float a3 = As[ty * 4 + 3][cc];
                const float4 b = *(const float4*)&Bs[cc][tx * 4];
                acc[0][0] += a0 * b.x; acc[0][1] += a0 * b.y; acc[0][2] += a0 * b.z; acc[0][3] += a0 * b.w;
                acc[1][0] += a1 * b.x; acc[1][1] += a1 * b.y; acc[1][2] += a1 * b.z; acc[1][3] += a1 * b.w;
                acc[2][0] += a2 * b.x; acc[2][1] += a2 * b.y; acc[2][2] += a2 * b.z; acc[2][3] += a2 * b.w;
                acc[3][0] += a3 * b.x; acc[3][1] += a3 * b.y; acc[3][2] += a3 * b.z; acc[3][3] += a3 * b.w;
            }
            __syncthreads();
        }
    }

    // --- epilogue ---
    #pragma unroll
    for (int i = 0; i < 4; ++i) {
        const long long row = n0 + ty * 4 + i;
        float4 v = make_float4(acc[i][0], acc[i][1], acc[i][2], acc[i][3]);
        if (MODE == 1) {
            const float4 s = *(const float4*)&skip[row * 64 + tx * 4];
            v.x += s.x; v.y += s.y; v.z += s.z; v.w += s.w;
        } else {
            v.x = v.x >= 0.f ? v.x : SLOPE * v.x;
            v.y = v.y >= 0.f ? v.y : SLOPE * v.y;
            v.z = v.z >= 0.f ? v.z : SLOPE * v.z;
            v.w = v.w >= 0.f ? v.w : SLOPE * v.w;
        }
        *(float4*)&out[row * 64 + tx * 4] = v;
    }
}

// ---------------------------------------------------------------------------
// BN stats: stage 1 — per-block partial sums / sumsq (deterministic, no atomics)
// ---------------------------------------------------------------------------
__global__ __launch_bounds__(256)
void reduce_stats(const float* __restrict__ t, int N, float* __restrict__ partial)
{
    const int ch  = threadIdx.x & 63;
    const int sub = threadIdx.x >> 6;    // 0..3
    float s = 0.f, ss = 0.f;
    for (int row = blockIdx.x * 4 + sub; row < N; row += gridDim.x * 4) {
        const float v = t[(long long)row * 64 + ch];
        s += v; ss += v * v;
    }
    __shared__ float sh[2][4][64];
    sh[0][sub][ch] = s;
    sh[1][sub][ch] = ss;
    __syncthreads();
    if (threadIdx.x < 64) {
        const float S  = sh[0][0][ch] + sh[0][1][ch] + sh[0][2][ch] + sh[0][3][ch];
        const float SS = sh[1][0][ch] + sh[1][1][ch] + sh[1][2][ch] + sh[1][3][ch];
        partial[blockIdx.x * 128 + ch]      = S;
        partial[blockIdx.x * 128 + 64 + ch] = SS;
    }
}

// Stage 2 — finalize mean/var -> affine a,b (64 threads, fixed order, double acc)
__global__ void finalize_stats(const float* __restrict__ partial, int nblk, float invN,
                               const float* __restrict__ gamma, const float* __restrict__ beta,
                               float* __restrict__ ab)
{
    const int ch = threadIdx.x;
    if (ch >= 64) return;
    double s = 0.0, ss = 0.0;
    for (int b = 0; b < nblk; ++b) {
        s  += (double)partial[b * 128 + ch];
        ss += (double)partial[b * 128 + 64 + ch];
    }
    const float m   = (float)(s * (double)invN);
    const float var = (float)(ss * (double)invN) - m * m;
    const float inv = rsqrtf(var + BN_EPS);
    const float a   = gamma[ch] * inv;
    ab[ch]      = a;
    ab[64 + ch] = beta[ch] - m * a;
}

// Final: out = t * a[ch] + b[ch]  (vectorized; 16 float4 per row of 64 channels)
__global__ __launch_bounds__(256)
void apply_affine(const float* __restrict__ t, const float* __restrict__ ab,
                  float* __restrict__ out, int total4)
{
    const int i = blockIdx.x * blockDim.x + threadIdx.x;
    if (i >= total4) return;
    float4 v = ((const float4*)t)[i];
    const int c = (i & 15) * 4;
    v.x = v.x * ab[c + 0] + ab[64 + c + 0];
    v.y = v.y * ab[c + 1] + ab[64 + c + 1];
    v.z = v.z * ab[c + 2] + ab[64 + c + 2];
    v.w = v.w * ab[c + 3] + ab[64 + c + 3];
    ((float4*)out)[i] = v;
}

// ---------------------------------------------------------------------------
extern "C" void kernel_launch(void* const* d_in, const int* in_sizes, int n_in,
                              void* d_out, int out_size)
{
    const float* x      = (const float*)d_in[0];
    const float* skip   = (const float*)d_in[1];
    const int*   nbr_t  = (const int*)d_in[2];
    const int*   nbr_up = (const int*)d_in[3];
    const int*   nbr1   = (const int*)d_in[4];
    const int*   nbr2   = (const int*)d_in[5];
    const int*   nbr3   = (const int*)d_in[6];
    const float* Wt     = (const float*)d_in[7];
    const float* Wu     = (const float*)d_in[8];
    const float* W1     = (const float*)d_in[9];
    const float* W2     = (const float*)d_in[10];
    const float* W3     = (const float*)d_in[11];
    const float* gt = (const float*)d_in[12]; const float* bt = (const float*)d_in[13];
    const float* g1 = (const float*)d_in[14]; const float* b1 = (const float*)d_in[15];
    const float* g2 = (const float*)d_in[16]; const float* b2 = (const float*)d_in[17];
    const float* g3 = (const float*)d_in[18]; const float* b3 = (const float*)d_in[19];

    const int N_in  = in_sizes[0] / 128;   // 80000
    const int N_out = in_sizes[1] / 64;    // 200000
    float* out = (float*)d_out;

    float *h_, *u_, *t1_, *t2_, *t3_, *part_, *ab_;
    cudaGetSymbolAddress((void**)&h_,    g_h);
    cudaGetSymbolAddress((void**)&u_,    g_u);
    cudaGetSymbolAddress((void**)&t1_,   g_t1);
    cudaGetSymbolAddress((void**)&t2_,   g_t2);
    cudaGetSymbolAddress((void**)&t3_,   g_t3);
    cudaGetSymbolAddress((void**)&part_, g_part);
    cudaGetSymbolAddress((void**)&ab_,   g_ab);

    const int gin  = N_in  / 64;   // 1250
    const int gout = N_out / 64;   // 3125

    // 1. trans conv (Cin=128) + lrelu -> g_h ; BN stats -> ab[0]
    conv_kernel<27, 128, false, 0><<<gin, 256>>>(x, Wt, nbr_t, nullptr, nullptr, h_, N_in, N_in);
    reduce_stats<<<RED_BLOCKS, 256>>>(h_, N_in, part_);
    finalize_stats<<<1, 64>>>(part_, RED_BLOCKS, 1.0f / N_in, gt, bt, ab_ + 0);

    // 2. inverse conv (gather of BN'd h) + skip -> g_u
    conv_kernel<27, 64, true, 1><<<gout, 256>>>(h_, Wu, nbr_up, ab_ + 0, skip, u_, N_in, N_out);

    // 3. conv1 + lrelu -> t1 ; stats -> ab[1]
    conv_kernel<9, 64, false, 0><<<gout, 256>>>(u_, W1, nbr1, nullptr, nullptr, t1_, N_out, N_out);
    reduce_stats<<<RED_BLOCKS, 256>>>(t1_, N_out, part_);
    finalize_stats<<<1, 64>>>(part_, RED_BLOCKS, 1.0f / N_out, g1, b1, ab_ + 128);

    // 4. conv2 (gather applies BN1) + lrelu -> t2 ; stats -> ab[2]
    conv_kernel<9, 64, true, 0><<<gout, 256>>>(t1_, W2, nbr2, ab_ + 128, nullptr, t2_, N_out, N_out);
    reduce_stats<<<RED_BLOCKS, 256>>>(t2_, N_out, part_);
    finalize_stats<<<1, 64>>>(part_, RED_BLOCKS, 1.0f / N_out, g2, b2, ab_ + 256);

    // 5. conv3 (gather applies BN2) + lrelu -> t3 ; stats -> ab[3]
    conv_kernel<27, 64, true, 0><<<gout, 256>>>(t2_, W3, nbr3, ab_ + 256, nullptr, t3_, N_out, N_out);
    reduce_stats<<<RED_BLOCKS, 256>>>(t3_, N_out, part_);
    finalize_stats<<<1, 64>>>(part_, RED_BLOCKS, 1.0f / N_out, g3, b3, ab_ + 384);

    // 6. final BN3 apply -> d_out
    const int total4 = N_out * 16;
    apply_affine<<<(total4 + 255) / 256, 256>>>(t3_, ab_ + 384, out, total4);
}